// round 1
// baseline (speedup 1.0000x reference)
#include <cuda_runtime.h>
#include <math.h>

#define NN 100000   // nodes
#define NE 500000   // edges
#define D  128      // in/out dim
#define A  64       // attn dim
#define NR 401      // rela vocab (2*200+1)
#define NQ 64       // queries
#define NT 366      // tau table size (0..365)

// ---------------- device scratch (static, allowed) ----------------
__device__ float g_agg [NN * D];
__device__ float g_aggs[NN * D];
__device__ float g_stab[NN * A];      // hidden @ Ws
__device__ float g_rattn[NR * A];     // rela_embed @ Wr
__device__ float g_qrattn[NQ * A];    // rela_embed[q_rel] @ Wqr + b
__device__ float g_tattn[NT * A];     // h_tau_tab @ Wtau
__device__ float g_htau [NT * D];     // h_tau table

// ---------------- kernels ----------------

__global__ void zero_kernel() {
    size_t i = (size_t)blockIdx.x * blockDim.x + threadIdx.x;
    size_t n4 = (size_t)NN * D / 4;
    float4 z = make_float4(0.f, 0.f, 0.f, 0.f);
    size_t stride = (size_t)gridDim.x * blockDim.x;
    for (size_t j = i; j < n4; j += stride) {
        reinterpret_cast<float4*>(g_agg)[j]  = z;
        reinterpret_cast<float4*>(g_aggs)[j] = z;
    }
}

// h_tau[t][d] = w1[d]*delta + b1[d] + sin(w2[d]*delta + b2[d]),  delta = t - q_tau
__global__ void htau_kernel(const float* __restrict__ w1, const float* __restrict__ b1,
                            const float* __restrict__ w2, const float* __restrict__ b2,
                            const int*   __restrict__ q_tau_p) {
    int t = blockIdx.x;
    int d = threadIdx.x;
    float qt = (float)q_tau_p[0];
    float delta = (float)t - qt;
    g_htau[t * D + d] = fmaf(w1[d], delta, b1[d]) + sinf(fmaf(w2[d], delta, b2[d]));
}

// out[r, :] = src[gather ? gather[r] : r, 0:128] @ W[128,64] (+ bias)
// 256 threads = 8 warps, warp per row, grid-stride.
__global__ void gemv64_kernel(const float* __restrict__ src, const int* __restrict__ gather,
                              const float* __restrict__ W,   const float* __restrict__ bias,
                              float* __restrict__ out, int nrows) {
    __shared__ float Wsm[D * A];       // 32 KB
    __shared__ float rowbuf[8][D];     // 4 KB
    int tid = threadIdx.x;
    for (int i = tid; i < D * A; i += blockDim.x) Wsm[i] = W[i];
    __syncthreads();
    int warp = tid >> 5, lane = tid & 31;
    float b0 = 0.f, b1 = 0.f;
    if (bias) { b0 = bias[2 * lane]; b1 = bias[2 * lane + 1]; }
    int gwarp = blockIdx.x * 8 + warp;
    int nwarps = gridDim.x * 8;
    for (int r = gwarp; r < nrows; r += nwarps) {
        int srow = gather ? gather[r] : r;
        reinterpret_cast<float4*>(rowbuf[warp])[lane] =
            reinterpret_cast<const float4*>(src + (size_t)srow * D)[lane];
        __syncwarp();
        float a0 = b0, a1 = b1;
#pragma unroll 4
        for (int k = 0; k < D; k++) {
            float h = rowbuf[warp][k];
            float2 w = *reinterpret_cast<const float2*>(&Wsm[k * A + 2 * lane]);
            a0 = fmaf(h, w.x, a0);
            a1 = fmaf(h, w.y, a1);
        }
        *reinterpret_cast<float2*>(&out[(size_t)r * A + 2 * lane]) = make_float2(a0, a1);
        __syncwarp();
    }
}

__device__ __forceinline__ void red4(float* p, float4 v) {
    asm volatile("red.global.add.v4.f32 [%0], {%1,%2,%3,%4};"
                 :: "l"(p), "f"(v.x), "f"(v.y), "f"(v.z), "f"(v.w) : "memory");
}

// warp per edge
__global__ void edge_kernel(const float* __restrict__ hidden, const int* __restrict__ edges,
                            const float* __restrict__ rela,
                            const float* __restrict__ w_alpha, const float* __restrict__ w_alpha_b,
                            const int* __restrict__ q_tau_p) {
    int gw = (blockIdx.x * blockDim.x + threadIdx.x) >> 5;
    int lane = threadIdx.x & 31;
    if (gw >= NE) return;
    const int* e = edges + (size_t)gw * 7;
    int ridx = __ldg(e + 0);
    int rel  = __ldg(e + 2);
    int tau  = __ldg(e + 4);
    int sub  = __ldg(e + 5);
    int obj  = __ldg(e + 6);
    int qt = __ldg(q_tau_p);
    int t = (tau >= 0) ? tau : qt;

    // attention (64 dims -> 2 per lane)
    float a0 = g_stab[(size_t)sub * A + lane]      + g_rattn[rel * A + lane]
             + g_qrattn[ridx * A + lane]           + g_tattn[t * A + lane];
    float a1 = g_stab[(size_t)sub * A + 32 + lane] + g_rattn[rel * A + 32 + lane]
             + g_qrattn[ridx * A + 32 + lane]      + g_tattn[t * A + 32 + lane];
    a0 = fmaxf(a0, 0.f);
    a1 = fmaxf(a1, 0.f);
    float p = fmaf(a0, __ldg(w_alpha + lane), a1 * __ldg(w_alpha + 32 + lane));
#pragma unroll
    for (int o = 16; o; o >>= 1) p += __shfl_xor_sync(0xffffffffu, p, o);
    float alpha = 1.f / (1.f + expf(-(p + __ldg(w_alpha_b))));
    float oma = 1.f - alpha;

    // message (128 dims -> float4 per lane)
    float4 hs = __ldg(reinterpret_cast<const float4*>(hidden + (size_t)sub * D) + lane);
    float4 hr = __ldg(reinterpret_cast<const float4*>(rela + (size_t)rel * D) + lane);
    float4 ht = *(reinterpret_cast<const float4*>(g_htau + (size_t)t * D) + lane);
    float4 m = make_float4(hs.x + hr.x + ht.x, hs.y + hr.y + ht.y,
                           hs.z + hr.z + ht.z, hs.w + hr.w + ht.w);
    float4 mm = make_float4(alpha * m.x, alpha * m.y, alpha * m.z, alpha * m.w);
    float4 ms = make_float4(oma * m.x, oma * m.y, oma * m.z, oma * m.w);

    red4(g_agg  + (size_t)obj * D + lane * 4, mm);
    red4(g_aggs + (size_t)obj * D + lane * 4, ms);
}

// fused epilogue: out[0:NN]   = g_agg  @ Wh   (128x128)
//                 out[NN:2NN] = g_aggs @ Whs  (128x128)
// 512 threads = 16 warps, warp per row, dynamic smem: both weights + row staging
__global__ void outgemm_kernel(const float* __restrict__ Wh, const float* __restrict__ Whs,
                               float* __restrict__ out) {
    extern __shared__ float sm[];
    float* Whm  = sm;                // 16384 floats
    float* Whsm = sm + D * D;        // 16384 floats
    float* rb   = sm + 2 * D * D;    // 16 warps * 256 floats
    int tid = threadIdx.x;
    for (int i = tid; i < D * D; i += blockDim.x) { Whm[i] = Wh[i]; Whsm[i] = Whs[i]; }
    __syncthreads();
    int warp = tid >> 5, lane = tid & 31;
    float* rba = rb + warp * 256;
    float* rbs = rba + 128;
    int nw = gridDim.x * (blockDim.x >> 5);
    for (int r = blockIdx.x * (blockDim.x >> 5) + warp; r < NN; r += nw) {
        reinterpret_cast<float4*>(rba)[lane] =
            reinterpret_cast<const float4*>(g_agg  + (size_t)r * D)[lane];
        reinterpret_cast<float4*>(rbs)[lane] =
            reinterpret_cast<const float4*>(g_aggs + (size_t)r * D)[lane];
        __syncwarp();
        float acc0 = 0, acc1 = 0, acc2 = 0, acc3 = 0;
        float as0 = 0, as1 = 0, as2 = 0, as3 = 0;
#pragma unroll 2
        for (int k = 0; k < D; k++) {
            float a = rba[k], b = rbs[k];
            float4 w  = *reinterpret_cast<const float4*>(&Whm [k * D + lane * 4]);
            float4 ws = *reinterpret_cast<const float4*>(&Whsm[k * D + lane * 4]);
            acc0 = fmaf(a, w.x, acc0);  acc1 = fmaf(a, w.y, acc1);
            acc2 = fmaf(a, w.z, acc2);  acc3 = fmaf(a, w.w, acc3);
            as0  = fmaf(b, ws.x, as0);  as1  = fmaf(b, ws.y, as1);
            as2  = fmaf(b, ws.z, as2);  as3  = fmaf(b, ws.w, as3);
        }
        reinterpret_cast<float4*>(out + (size_t)r * D)[lane] =
            make_float4(acc0, acc1, acc2, acc3);
        reinterpret_cast<float4*>(out + (size_t)NN * D + (size_t)r * D)[lane] =
            make_float4(as0, as1, as2, as3);
        __syncwarp();
    }
}

// ---------------- launch ----------------
extern "C" void kernel_launch(void* const* d_in, const int* in_sizes, int n_in,
                              void* d_out, int out_size) {
    // metadata order (setup_inputs dict order)
    const int*   q_rel     = (const int*)  d_in[1];
    const int*   q_tau     = (const int*)  d_in[2];
    const float* hidden    = (const float*)d_in[3];
    const int*   edges     = (const int*)  d_in[4];
    const float* rela      = (const float*)d_in[7];
    const float* Ws_w      = (const float*)d_in[8];
    const float* Wr_w      = (const float*)d_in[9];
    const float* Wqr_w     = (const float*)d_in[10];
    const float* Wqr_b     = (const float*)d_in[11];
    const float* Wtau_w    = (const float*)d_in[12];
    const float* w_alpha_w = (const float*)d_in[13];
    const float* w_alpha_b = (const float*)d_in[14];
    const float* W_h_w     = (const float*)d_in[15];
    const float* W_h_s_w   = (const float*)d_in[16];
    const float* wt1       = (const float*)d_in[17];
    const float* bt1       = (const float*)d_in[18];
    const float* wt2       = (const float*)d_in[19];
    const float* bt2       = (const float*)d_in[20];
    float* out = (float*)d_out;

    float *p_stab, *p_rattn, *p_qrattn, *p_tattn, *p_htau;
    cudaGetSymbolAddress((void**)&p_stab,   g_stab);
    cudaGetSymbolAddress((void**)&p_rattn,  g_rattn);
    cudaGetSymbolAddress((void**)&p_qrattn, g_qrattn);
    cudaGetSymbolAddress((void**)&p_tattn,  g_tattn);
    cudaGetSymbolAddress((void**)&p_htau,   g_htau);

    // 1) zero accumulators
    zero_kernel<<<1024, 256>>>();
    // 2) h_tau table
    htau_kernel<<<NT, D>>>(wt1, bt1, wt2, bt2, q_tau);
    // 3) attention tables
    gemv64_kernel<<<(NN + 7) / 8, 256>>>(hidden, nullptr, Ws_w, nullptr, p_stab, NN);
    gemv64_kernel<<<(NR + 7) / 8, 256>>>(rela, nullptr, Wr_w, nullptr, p_rattn, NR);
    gemv64_kernel<<<(NT + 7) / 8, 256>>>(p_htau, nullptr, Wtau_w, nullptr, p_tattn, NT);
    gemv64_kernel<<<(NQ + 7) / 8, 256>>>(rela, q_rel, Wqr_w, Wqr_b, p_qrattn, NQ);
    // 4) edge scatter
    edge_kernel<<<NE / 8, 256>>>(hidden, edges, rela, w_alpha_w, w_alpha_b, q_tau);
    // 5) fused epilogue GEMMs
    int smem = (2 * D * D + 16 * 256) * (int)sizeof(float);   // 147456 B
    cudaFuncSetAttribute(outgemm_kernel, cudaFuncAttributeMaxDynamicSharedMemorySize, smem);
    outgemm_kernel<<<148, 512, smem>>>(W_h_w, W_h_s_w, out);
}

// round 4
// speedup vs baseline: 1.7739x; 1.7739x over previous
#include <cuda_runtime.h>
#include <math.h>

#define NN 100000   // nodes
#define NE 500000   // edges
#define D  128      // in/out dim
#define A  64       // attn dim
#define NR 401      // rela vocab
#define NQ 64       // queries
#define NT 366      // tau table

typedef unsigned long long ull;

// ---------------- device scratch ----------------
__device__ float g_agg [NN * D];
__device__ float g_aggs[NN * D];
__device__ float g_stab[NN * A];      // hidden @ Ws
__device__ float g_rattn[NR * A];     // rela @ Wr
__device__ float g_qrattn[NQ * A];    // rela[q_rel] @ Wqr + b
__device__ float g_tattn[NT * A];     // h_tau @ Wtau
__device__ float g_htau [NT * D];

// ---------------- f32x2 helpers (B300 FFMA2) ----------------
__device__ __forceinline__ ull dup2(float a) {
    ull r; asm("mov.b64 %0, {%1,%1};" : "=l"(r) : "f"(a)); return r;
}
__device__ __forceinline__ void ffma2(ull& acc, ull a, ull b) {
    asm("fma.rn.f32x2 %0, %1, %2, %0;" : "+l"(acc) : "l"(a), "l"(b));
}

// ---------------- zero accumulators ----------------
__global__ void zero_kernel() {
    size_t i = (size_t)blockIdx.x * blockDim.x + threadIdx.x;
    size_t n4 = (size_t)NN * D / 4;
    float4 z = make_float4(0.f, 0.f, 0.f, 0.f);
    size_t stride = (size_t)gridDim.x * blockDim.x;
    for (size_t j = i; j < n4; j += stride) {
        reinterpret_cast<float4*>(g_agg)[j]  = z;
        reinterpret_cast<float4*>(g_aggs)[j] = z;
    }
}

// ---------------- h_tau table ----------------
__global__ void htau_kernel(const float* __restrict__ w1, const float* __restrict__ b1,
                            const float* __restrict__ w2, const float* __restrict__ b2,
                            const int*   __restrict__ q_tau_p) {
    int t = blockIdx.x;
    int d = threadIdx.x;
    float qt = (float)q_tau_p[0];
    float delta = (float)t - qt;
    g_htau[t * D + d] = fmaf(w1[d], delta, b1[d]) + sinf(fmaf(w2[d], delta, b2[d]));
}

// ---------------- combined small attention tables ----------------
// blocks 0..50 -> rattn (401 rows), 51..96 -> tattn (366), 97..104 -> qrattn (64)
__global__ void smalltab_kernel(const float* __restrict__ rela, const int* __restrict__ q_rel,
                                const float* __restrict__ Wr,   const float* __restrict__ Wtau,
                                const float* __restrict__ Wqr,  const float* __restrict__ Wqr_b) {
    __shared__ float Wsm[D * A];
    __shared__ float rowbuf[8][D];
    const float* src; const float* W; const float* bias; const int* gather;
    float* out; int rows; int base; int nblk;
    int b = blockIdx.x;
    if (b < 51)      { src = rela;   W = Wr;   bias = nullptr; gather = nullptr; out = g_rattn;  rows = NR; base = 0;  nblk = 51; }
    else if (b < 97) { src = g_htau; W = Wtau; bias = nullptr; gather = nullptr; out = g_tattn;  rows = NT; base = 51; nblk = 46; }
    else             { src = rela;   W = Wqr;  bias = Wqr_b;   gather = q_rel;   out = g_qrattn; rows = NQ; base = 97; nblk = 8;  }

    int tid = threadIdx.x;
    for (int i = tid; i < D * A; i += blockDim.x) Wsm[i] = W[i];
    __syncthreads();
    int warp = tid >> 5, lane = tid & 31;
    float b0 = 0.f, b1 = 0.f;
    if (bias) { b0 = bias[2 * lane]; b1 = bias[2 * lane + 1]; }
    int gwarp = (b - base) * 8 + warp;
    int nwarps = nblk * 8;
    for (int r = gwarp; r < rows; r += nwarps) {
        int srow = gather ? gather[r] : r;
        reinterpret_cast<float4*>(rowbuf[warp])[lane] =
            reinterpret_cast<const float4*>(src + (size_t)srow * D)[lane];
        __syncwarp();
        float a0 = b0, a1 = b1;
#pragma unroll 4
        for (int k = 0; k < D; k++) {
            float h = rowbuf[warp][k];
            float2 w = *reinterpret_cast<const float2*>(&Wsm[k * A + 2 * lane]);
            a0 = fmaf(h, w.x, a0);
            a1 = fmaf(h, w.y, a1);
        }
        *reinterpret_cast<float2*>(&out[(size_t)r * A + 2 * lane]) = make_float2(a0, a1);
        __syncwarp();
    }
}

// ---------------- tiled stab GEMM: g_stab = hidden @ Ws  (NN x 128 @ 128 x 64) ----------------
// 64-row tiles, 256 threads, thread = 4 rows x 4 cols, f32x2 accumulators.
__global__ void __launch_bounds__(256) stab_kernel(const float* __restrict__ hidden,
                                                   const float* __restrict__ Ws) {
    extern __shared__ float sm[];
    float* Wsm = sm;               // 128*64
    float* As  = sm + 128 * A;     // 64*132
    int tid = threadIdx.x;
    for (int i = tid; i < 128 * A / 4; i += 256)
        reinterpret_cast<float4*>(Wsm)[i] = reinterpret_cast<const float4*>(Ws)[i];
    int rbase = blockIdx.x * 64;
#pragma unroll
    for (int i = 0; i < 8; i++) {
        int fid = tid + i * 256;
        int r = fid >> 5, c4 = fid & 31;
        float4 v = make_float4(0.f, 0.f, 0.f, 0.f);
        if (rbase + r < NN)
            v = reinterpret_cast<const float4*>(hidden + (size_t)(rbase + r) * D)[c4];
        *reinterpret_cast<float4*>(&As[r * 132 + c4 * 4]) = v;
    }
    __syncthreads();
    int tx = tid & 15, ty = tid >> 4;
    int c0 = tx * 4, r0 = ty * 4;
    ull acc[4][2];
#pragma unroll
    for (int r = 0; r < 4; r++) { acc[r][0] = 0ull; acc[r][1] = 0ull; }
    for (int kk = 0; kk < 32; kk++) {
        int k0 = kk * 4;
        ulonglong2 w[4];
#pragma unroll
        for (int j = 0; j < 4; j++)
            w[j] = *reinterpret_cast<const ulonglong2*>(&Wsm[(k0 + j) * A + c0]);
#pragma unroll
        for (int r = 0; r < 4; r++) {
            float4 a4 = *reinterpret_cast<const float4*>(&As[(r0 + r) * 132 + k0]);
            ull d;
            d = dup2(a4.x); ffma2(acc[r][0], d, w[0].x); ffma2(acc[r][1], d, w[0].y);
            d = dup2(a4.y); ffma2(acc[r][0], d, w[1].x); ffma2(acc[r][1], d, w[1].y);
            d = dup2(a4.z); ffma2(acc[r][0], d, w[2].x); ffma2(acc[r][1], d, w[2].y);
            d = dup2(a4.w); ffma2(acc[r][0], d, w[3].x); ffma2(acc[r][1], d, w[3].y);
        }
    }
#pragma unroll
    for (int r = 0; r < 4; r++) {
        int row = rbase + r0 + r;
        if (row < NN)
            *reinterpret_cast<ulonglong2*>(&g_stab[(size_t)row * A + c0]) =
                make_ulonglong2(acc[r][0], acc[r][1]);
    }
}

// ---------------- edge scatter ----------------
__device__ __forceinline__ void red4(float* p, float4 v) {
    asm volatile("red.global.add.v4.f32 [%0], {%1,%2,%3,%4};"
                 :: "l"(p), "f"(v.x), "f"(v.y), "f"(v.z), "f"(v.w) : "memory");
}

__global__ void edge_kernel(const float* __restrict__ hidden, const int* __restrict__ edges,
                            const float* __restrict__ rela,
                            const float* __restrict__ w_alpha, const float* __restrict__ w_alpha_b,
                            const int* __restrict__ q_tau_p) {
    int gw = (blockIdx.x * blockDim.x + threadIdx.x) >> 5;
    int lane = threadIdx.x & 31;
    if (gw >= NE) return;
    const int* e = edges + (size_t)gw * 7;
    int ridx = __ldg(e + 0);
    int rel  = __ldg(e + 2);
    int tau  = __ldg(e + 4);
    int sub  = __ldg(e + 5);
    int obj  = __ldg(e + 6);
    int qt = __ldg(q_tau_p);
    int t = (tau >= 0) ? tau : qt;

    float a0 = g_stab[(size_t)sub * A + lane]      + g_rattn[rel * A + lane]
             + g_qrattn[ridx * A + lane]           + g_tattn[t * A + lane];
    float a1 = g_stab[(size_t)sub * A + 32 + lane] + g_rattn[rel * A + 32 + lane]
             + g_qrattn[ridx * A + 32 + lane]      + g_tattn[t * A + 32 + lane];
    a0 = fmaxf(a0, 0.f);
    a1 = fmaxf(a1, 0.f);
    float p = fmaf(a0, __ldg(w_alpha + lane), a1 * __ldg(w_alpha + 32 + lane));
#pragma unroll
    for (int o = 16; o; o >>= 1) p += __shfl_xor_sync(0xffffffffu, p, o);
    float alpha = 1.f / (1.f + expf(-(p + __ldg(w_alpha_b))));
    float oma = 1.f - alpha;

    float4 hs = __ldg(reinterpret_cast<const float4*>(hidden + (size_t)sub * D) + lane);
    float4 hr = __ldg(reinterpret_cast<const float4*>(rela + (size_t)rel * D) + lane);
    float4 ht = *(reinterpret_cast<const float4*>(g_htau + (size_t)t * D) + lane);
    float4 m = make_float4(hs.x + hr.x + ht.x, hs.y + hr.y + ht.y,
                           hs.z + hr.z + ht.z, hs.w + hr.w + ht.w);
    float4 mm = make_float4(alpha * m.x, alpha * m.y, alpha * m.z, alpha * m.w);
    float4 ms = make_float4(oma * m.x, oma * m.y, oma * m.z, oma * m.w);

    red4(g_agg  + (size_t)obj * D + lane * 4, mm);
    red4(g_aggs + (size_t)obj * D + lane * 4, ms);
}

// ---------------- tiled epilogue: out = [agg@Wh ; aggs@Whs] ----------------
// persistent blocks, 64-row tiles, thread = 8 rows x 4 cols x 2 matrices, f32x2.
__global__ void __launch_bounds__(256) epi_kernel(const float* __restrict__ Wh,
                                                  const float* __restrict__ Whs,
                                                  float* __restrict__ out) {
    extern __shared__ float sm[];
    float* Whm  = sm;                    // 16384
    float* Whsm = sm + 16384;            // 16384
    float* Aa   = sm + 32768;            // 64*132 = 8448
    float* Ab   = Aa + 8448;             // 8448
    int tid = threadIdx.x;
    for (int i = tid; i < 16384 / 4; i += 256) {
        reinterpret_cast<float4*>(Whm)[i]  = reinterpret_cast<const float4*>(Wh)[i];
        reinterpret_cast<float4*>(Whsm)[i] = reinterpret_cast<const float4*>(Whs)[i];
    }
    int tx = tid & 31, ty = tid >> 5;
    int c0 = tx * 4, r0 = ty * 8;
    const int ntile = (NN + 63) / 64;
    for (int tile = blockIdx.x; tile < ntile; tile += gridDim.x) {
        int rbase = tile * 64;
        __syncthreads();   // covers weight load on first iter; Aa/Ab reuse after
#pragma unroll
        for (int i = 0; i < 8; i++) {
            int fid = tid + i * 256;
            int r = fid >> 5, c4 = fid & 31;
            float4 va = make_float4(0.f, 0.f, 0.f, 0.f), vb = va;
            if (rbase + r < NN) {
                va = reinterpret_cast<const float4*>(g_agg  + (size_t)(rbase + r) * D)[c4];
                vb = reinterpret_cast<const float4*>(g_aggs + (size_t)(rbase + r) * D)[c4];
            }
            *reinterpret_cast<float4*>(&Aa[r * 132 + c4 * 4]) = va;
            *reinterpret_cast<float4*>(&Ab[r * 132 + c4 * 4]) = vb;
        }
        __syncthreads();
        ull accA[8][2], accB[8][2];
#pragma unroll
        for (int r = 0; r < 8; r++) { accA[r][0] = accA[r][1] = 0ull; accB[r][0] = accB[r][1] = 0ull; }
        for (int kk = 0; kk < 32; kk++) {
            int k0 = kk * 4;
            ulonglong2 wA[4], wB[4];
#pragma unroll
            for (int j = 0; j < 4; j++) {
                wA[j] = *reinterpret_cast<const ulonglong2*>(&Whm [(k0 + j) * D + c0]);
                wB[j] = *reinterpret_cast<const ulonglong2*>(&Whsm[(k0 + j) * D + c0]);
            }
#pragma unroll
            for (int r = 0; r < 8; r++) {
                float4 a4 = *reinterpret_cast<const float4*>(&Aa[(r0 + r) * 132 + k0]);
                float4 b4 = *reinterpret_cast<const float4*>(&Ab[(r0 + r) * 132 + k0]);
                ull d;
                d = dup2(a4.x); ffma2(accA[r][0], d, wA[0].x); ffma2(accA[r][1], d, wA[0].y);
                d = dup2(a4.y); ffma2(accA[r][0], d, wA[1].x); ffma2(accA[r][1], d, wA[1].y);
                d = dup2(a4.z); ffma2(accA[r][0], d, wA[2].x); ffma2(accA[r][1], d, wA[2].y);
                d = dup2(a4.w); ffma2(accA[r][0], d, wA[3].x); ffma2(accA[r][1], d, wA[3].y);
                d = dup2(b4.x); ffma2(accB[r][0], d, wB[0].x); ffma2(accB[r][1], d, wB[0].y);
                d = dup2(b4.y); ffma2(accB[r][0], d, wB[1].x); ffma2(accB[r][1], d, wB[1].y);
                d = dup2(b4.z); ffma2(accB[r][0], d, wB[2].x); ffma2(accB[r][1], d, wB[2].y);
                d = dup2(b4.w); ffma2(accB[r][0], d, wB[3].x); ffma2(accB[r][1], d, wB[3].y);
            }
        }
#pragma unroll
        for (int r = 0; r < 8; r++) {
            int row = rbase + r0 + r;
            if (row < NN) {
                *reinterpret_cast<ulonglong2*>(&out[(size_t)row * D + c0]) =
                    make_ulonglong2(accA[r][0], accA[r][1]);
                *reinterpret_cast<ulonglong2*>(&out[(size_t)(NN + row) * D + c0]) =
                    make_ulonglong2(accB[r][0], accB[r][1]);
            }
        }
    }
}

// ---------------- launch ----------------
extern "C" void kernel_launch(void* const* d_in, const int* in_sizes, int n_in,
                              void* d_out, int out_size) {
    const int*   q_rel     = (const int*)  d_in[1];
    const int*   q_tau     = (const int*)  d_in[2];
    const float* hidden    = (const float*)d_in[3];
    const int*   edges     = (const int*)  d_in[4];
    const float* rela      = (const float*)d_in[7];
    const float* Ws_w      = (const float*)d_in[8];
    const float* Wr_w      = (const float*)d_in[9];
    const float* Wqr_w     = (const float*)d_in[10];
    const float* Wqr_b     = (const float*)d_in[11];
    const float* Wtau_w    = (const float*)d_in[12];
    const float* w_alpha_w = (const float*)d_in[13];
    const float* w_alpha_b = (const float*)d_in[14];
    const float* W_h_w     = (const float*)d_in[15];
    const float* W_h_s_w   = (const float*)d_in[16];
    const float* wt1       = (const float*)d_in[17];
    const float* bt1       = (const float*)d_in[18];
    const float* wt2       = (const float*)d_in[19];
    const float* bt2       = (const float*)d_in[20];
    float* out = (float*)d_out;

    int stab_smem = (128 * A + 64 * 132) * (int)sizeof(float);            // 66560
    int epi_smem  = (2 * 16384 + 2 * 8448) * (int)sizeof(float);          // 198656
    cudaFuncSetAttribute(stab_kernel, cudaFuncAttributeMaxDynamicSharedMemorySize, stab_smem);
    cudaFuncSetAttribute(epi_kernel,  cudaFuncAttributeMaxDynamicSharedMemorySize, epi_smem);

    zero_kernel<<<1024, 256>>>();
    htau_kernel<<<NT, D>>>(wt1, bt1, wt2, bt2, q_tau);
    smalltab_kernel<<<105, 256>>>(rela, q_rel, Wr_w, Wtau_w, Wqr_w, Wqr_b);
    stab_kernel<<<(NN + 63) / 64, 256, stab_smem>>>(hidden, Ws_w);
    edge_kernel<<<NE / 8, 256>>>(hidden, edges, rela, w_alpha_w, w_alpha_b, q_tau);
    epi_kernel<<<148, 256, epi_smem>>>(W_h_w, W_h_s_w, out);
}

// round 5
// speedup vs baseline: 1.8807x; 1.0602x over previous
#include <cuda_runtime.h>
#include <math.h>

#define NN 100000   // nodes
#define NE 500000   // edges
#define D  128      // in/out dim
#define A  64       // attn dim
#define NR 401      // rela vocab
#define NQ 64       // queries
#define NT 366      // tau table

#define STAB_B 1563
#define TAB_B  105
#define ZERO_B 256
#define HTAU_B 183
#define PREP_GRID (STAB_B + TAB_B + ZERO_B + HTAU_B)

typedef unsigned long long ull;

// ---------------- device scratch ----------------
__device__ float g_agg [NN * D];
__device__ float g_aggs[NN * D];
__device__ float g_stab[NN * A];      // hidden @ Ws
__device__ float g_rattn[NR * A];     // rela @ Wr
__device__ float g_qrattn[NQ * A];    // rela[q_rel] @ Wqr + b
__device__ float g_tattn[NT * A];     // h_tau @ Wtau
__device__ float g_htau [NT * D];

// ---------------- f32x2 helpers (B300 FFMA2) ----------------
__device__ __forceinline__ ull dup2(float a) {
    ull r; asm("mov.b64 %0, {%1,%1};" : "=l"(r) : "f"(a)); return r;
}
__device__ __forceinline__ void ffma2(ull& acc, ull a, ull b) {
    asm("fma.rn.f32x2 %0, %1, %2, %0;" : "+l"(acc) : "l"(a), "l"(b));
}

// ============ fused prep kernel: stab GEMM | small tables | zero | htau ============
__global__ void __launch_bounds__(256) prep_kernel(
    const float* __restrict__ hidden, const float* __restrict__ Ws,
    const float* __restrict__ rela,   const int*   __restrict__ q_rel,
    const float* __restrict__ Wr,     const float* __restrict__ Wtau,
    const float* __restrict__ Wqr,    const float* __restrict__ Wqr_b,
    const float* __restrict__ w1, const float* __restrict__ b1,
    const float* __restrict__ w2, const float* __restrict__ b2,
    const int* __restrict__ q_tau_p)
{
    extern __shared__ float sm[];
    int b = blockIdx.x;
    int tid = threadIdx.x;

    if (b < STAB_B) {
        // ---- stab: g_stab = hidden @ Ws (64-row tile, thread = 4r x 4c, f32x2) ----
        float* Wsm = sm;               // 128*64
        float* As  = sm + 128 * A;     // 64*132
        for (int i = tid; i < 128 * A / 4; i += 256)
            reinterpret_cast<float4*>(Wsm)[i] = reinterpret_cast<const float4*>(Ws)[i];
        int rbase = b * 64;
#pragma unroll
        for (int i = 0; i < 8; i++) {
            int fid = tid + i * 256;
            int r = fid >> 5, c4 = fid & 31;
            float4 v = make_float4(0.f, 0.f, 0.f, 0.f);
            if (rbase + r < NN)
                v = reinterpret_cast<const float4*>(hidden + (size_t)(rbase + r) * D)[c4];
            *reinterpret_cast<float4*>(&As[r * 132 + c4 * 4]) = v;
        }
        __syncthreads();
        int tx = tid & 15, ty = tid >> 4;
        int c0 = tx * 4, r0 = ty * 4;
        ull acc[4][2];
#pragma unroll
        for (int r = 0; r < 4; r++) { acc[r][0] = 0ull; acc[r][1] = 0ull; }
        for (int kk = 0; kk < 32; kk++) {
            int k0 = kk * 4;
            ulonglong2 w[4];
#pragma unroll
            for (int j = 0; j < 4; j++)
                w[j] = *reinterpret_cast<const ulonglong2*>(&Wsm[(k0 + j) * A + c0]);
#pragma unroll
            for (int r = 0; r < 4; r++) {
                float4 a4 = *reinterpret_cast<const float4*>(&As[(r0 + r) * 132 + k0]);
                ull d;
                d = dup2(a4.x); ffma2(acc[r][0], d, w[0].x); ffma2(acc[r][1], d, w[0].y);
                d = dup2(a4.y); ffma2(acc[r][0], d, w[1].x); ffma2(acc[r][1], d, w[1].y);
                d = dup2(a4.z); ffma2(acc[r][0], d, w[2].x); ffma2(acc[r][1], d, w[2].y);
                d = dup2(a4.w); ffma2(acc[r][0], d, w[3].x); ffma2(acc[r][1], d, w[3].y);
            }
        }
#pragma unroll
        for (int r = 0; r < 4; r++) {
            int row = rbase + r0 + r;
            if (row < NN)
                *reinterpret_cast<ulonglong2*>(&g_stab[(size_t)row * A + c0]) =
                    make_ulonglong2(acc[r][0], acc[r][1]);
        }
        return;
    }
    b -= STAB_B;

    if (b < TAB_B) {
        // ---- small attention tables: rattn / tattn (inline h_tau) / qrattn ----
        float* Wsm = sm;               // D*A
        float* rowbuf = sm + D * A;    // 8*D
        const float* src = nullptr; const float* W; const float* bias = nullptr;
        const int* gather = nullptr;
        float* out; int rows; int base; int nblk; bool comp_tau = false;
        if (b < 51)      { src = rela; W = Wr;   out = g_rattn;  rows = NR; base = 0;  nblk = 51; }
        else if (b < 97) { comp_tau = true; W = Wtau; out = g_tattn; rows = NT; base = 51; nblk = 46; }
        else             { src = rela; W = Wqr; bias = Wqr_b; gather = q_rel;
                           out = g_qrattn; rows = NQ; base = 97; nblk = 8; }

        for (int i = tid; i < D * A; i += 256) Wsm[i] = W[i];
        __syncthreads();
        int warp = tid >> 5, lane = tid & 31;
        float b0 = 0.f, b1v = 0.f;
        if (bias) { b0 = bias[2 * lane]; b1v = bias[2 * lane + 1]; }
        float qt = (float)__ldg(q_tau_p);
        int gwarp = (b - base) * 8 + warp;
        int nwarps = nblk * 8;
        for (int r = gwarp; r < rows; r += nwarps) {
            if (comp_tau) {
                float delta = (float)r - qt;
                float4 a1 = __ldg(reinterpret_cast<const float4*>(w1) + lane);
                float4 c1 = __ldg(reinterpret_cast<const float4*>(b1) + lane);
                float4 a2 = __ldg(reinterpret_cast<const float4*>(w2) + lane);
                float4 c2 = __ldg(reinterpret_cast<const float4*>(b2) + lane);
                float4 v;
                v.x = fmaf(a1.x, delta, c1.x) + sinf(fmaf(a2.x, delta, c2.x));
                v.y = fmaf(a1.y, delta, c1.y) + sinf(fmaf(a2.y, delta, c2.y));
                v.z = fmaf(a1.z, delta, c1.z) + sinf(fmaf(a2.z, delta, c2.z));
                v.w = fmaf(a1.w, delta, c1.w) + sinf(fmaf(a2.w, delta, c2.w));
                reinterpret_cast<float4*>(&rowbuf[warp * D])[lane] = v;
            } else {
                int srow = gather ? gather[r] : r;
                reinterpret_cast<float4*>(&rowbuf[warp * D])[lane] =
                    reinterpret_cast<const float4*>(src + (size_t)srow * D)[lane];
            }
            __syncwarp();
            float a0 = b0, a1s = b1v;
#pragma unroll 4
            for (int k = 0; k < D; k++) {
                float h = rowbuf[warp * D + k];
                float2 w = *reinterpret_cast<const float2*>(&Wsm[k * A + 2 * lane]);
                a0  = fmaf(h, w.x, a0);
                a1s = fmaf(h, w.y, a1s);
            }
            *reinterpret_cast<float2*>(&out[(size_t)r * A + 2 * lane]) = make_float2(a0, a1s);
            __syncwarp();
        }
        return;
    }
    b -= TAB_B;

    if (b < ZERO_B) {
        // ---- zero accumulators ----
        size_t i = (size_t)b * 256 + tid;
        size_t n4 = (size_t)NN * D / 4;
        size_t stride = (size_t)ZERO_B * 256;
        float4 z = make_float4(0.f, 0.f, 0.f, 0.f);
        for (size_t j = i; j < n4; j += stride) {
            reinterpret_cast<float4*>(g_agg)[j]  = z;
            reinterpret_cast<float4*>(g_aggs)[j] = z;
        }
        return;
    }
    b -= ZERO_B;

    // ---- htau table (for edge kernel) ----
    int idx = b * 256 + tid;
    if (idx < NT * D) {
        int t = idx >> 7, d = idx & 127;
        float qt = (float)__ldg(q_tau_p);
        float delta = (float)t - qt;
        g_htau[idx] = fmaf(w1[d], delta, b1[d]) + sinf(fmaf(w2[d], delta, b2[d]));
    }
}

// ---------------- edge scatter ----------------
__device__ __forceinline__ void red4(float* p, float4 v) {
    asm volatile("red.global.add.v4.f32 [%0], {%1,%2,%3,%4};"
                 :: "l"(p), "f"(v.x), "f"(v.y), "f"(v.z), "f"(v.w) : "memory");
}

__global__ void edge_kernel(const float* __restrict__ hidden, const int* __restrict__ edges,
                            const float* __restrict__ rela,
                            const float* __restrict__ w_alpha, const float* __restrict__ w_alpha_b,
                            const int* __restrict__ q_tau_p) {
    int gw = (blockIdx.x * blockDim.x + threadIdx.x) >> 5;
    int lane = threadIdx.x & 31;
    if (gw >= NE) return;
    const int* e = edges + (size_t)gw * 7;
    int ridx = __ldg(e + 0);
    int rel  = __ldg(e + 2);
    int tau  = __ldg(e + 4);
    int sub  = __ldg(e + 5);
    int obj  = __ldg(e + 6);
    int qt = __ldg(q_tau_p);
    int t = (tau >= 0) ? tau : qt;

    float a0 = g_stab[(size_t)sub * A + lane]      + g_rattn[rel * A + lane]
             + g_qrattn[ridx * A + lane]           + g_tattn[t * A + lane];
    float a1 = g_stab[(size_t)sub * A + 32 + lane] + g_rattn[rel * A + 32 + lane]
             + g_qrattn[ridx * A + 32 + lane]      + g_tattn[t * A + 32 + lane];
    a0 = fmaxf(a0, 0.f);
    a1 = fmaxf(a1, 0.f);
    float p = fmaf(a0, __ldg(w_alpha + lane), a1 * __ldg(w_alpha + 32 + lane));
#pragma unroll
    for (int o = 16; o; o >>= 1) p += __shfl_xor_sync(0xffffffffu, p, o);
    float alpha = 1.f / (1.f + expf(-(p + __ldg(w_alpha_b))));
    float oma = 1.f - alpha;

    float4 hs = __ldg(reinterpret_cast<const float4*>(hidden + (size_t)sub * D) + lane);
    float4 hr = __ldg(reinterpret_cast<const float4*>(rela + (size_t)rel * D) + lane);
    float4 ht = *(reinterpret_cast<const float4*>(g_htau + (size_t)t * D) + lane);
    float4 m = make_float4(hs.x + hr.x + ht.x, hs.y + hr.y + ht.y,
                           hs.z + hr.z + ht.z, hs.w + hr.w + ht.w);
    float4 mm = make_float4(alpha * m.x, alpha * m.y, alpha * m.z, alpha * m.w);
    float4 ms = make_float4(oma * m.x, oma * m.y, oma * m.z, oma * m.w);

    red4(g_agg  + (size_t)obj * D + lane * 4, mm);
    red4(g_aggs + (size_t)obj * D + lane * 4, ms);
}

// ---------------- tiled epilogue: out = [agg@Wh ; aggs@Whs] ----------------
// persistent blocks, 512 threads (16 warps), 64-row tiles, thread = 4r x 4c x 2 mats.
__global__ void __launch_bounds__(512) epi_kernel(const float* __restrict__ Wh,
                                                  const float* __restrict__ Whs,
                                                  float* __restrict__ out) {
    extern __shared__ float sm[];
    float* Whm  = sm;                    // 16384
    float* Whsm = sm + 16384;            // 16384
    float* Aa   = sm + 32768;            // 64*132 = 8448
    float* Ab   = Aa + 8448;             // 8448
    int tid = threadIdx.x;
    for (int i = tid; i < 16384 / 4; i += 512) {
        reinterpret_cast<float4*>(Whm)[i]  = reinterpret_cast<const float4*>(Wh)[i];
        reinterpret_cast<float4*>(Whsm)[i] = reinterpret_cast<const float4*>(Whs)[i];
    }
    int tx = tid & 31, ty = tid >> 5;          // tx: 32 col groups, ty: 16 row groups
    int c0 = tx * 4, r0 = ty * 4;
    const int ntile = (NN + 63) / 64;
    for (int tile = blockIdx.x; tile < ntile; tile += gridDim.x) {
        int rbase = tile * 64;
        __syncthreads();   // covers weight load on first iter; Aa/Ab reuse after
#pragma unroll
        for (int i = 0; i < 4; i++) {
            int fid = tid + i * 512;
            int r = fid >> 5, c4 = fid & 31;
            float4 va = make_float4(0.f, 0.f, 0.f, 0.f), vb = va;
            if (rbase + r < NN) {
                va = reinterpret_cast<const float4*>(g_agg  + (size_t)(rbase + r) * D)[c4];
                vb = reinterpret_cast<const float4*>(g_aggs + (size_t)(rbase + r) * D)[c4];
            }
            *reinterpret_cast<float4*>(&Aa[r * 132 + c4 * 4]) = va;
            *reinterpret_cast<float4*>(&Ab[r * 132 + c4 * 4]) = vb;
        }
        __syncthreads();
        ull accA[4][2], accB[4][2];
#pragma unroll
        for (int r = 0; r < 4; r++) { accA[r][0] = accA[r][1] = 0ull; accB[r][0] = accB[r][1] = 0ull; }
        for (int kk = 0; kk < 32; kk++) {
            int k0 = kk * 4;
            ulonglong2 wA[4], wB[4];
#pragma unroll
            for (int j = 0; j < 4; j++) {
                wA[j] = *reinterpret_cast<const ulonglong2*>(&Whm [(k0 + j) * D + c0]);
                wB[j] = *reinterpret_cast<const ulonglong2*>(&Whsm[(k0 + j) * D + c0]);
            }
#pragma unroll
            for (int r = 0; r < 4; r++) {
                float4 a4 = *reinterpret_cast<const float4*>(&Aa[(r0 + r) * 132 + k0]);
                float4 b4 = *reinterpret_cast<const float4*>(&Ab[(r0 + r) * 132 + k0]);
                ull d;
                d = dup2(a4.x); ffma2(accA[r][0], d, wA[0].x); ffma2(accA[r][1], d, wA[0].y);
                d = dup2(a4.y); ffma2(accA[r][0], d, wA[1].x); ffma2(accA[r][1], d, wA[1].y);
                d = dup2(a4.z); ffma2(accA[r][0], d, wA[2].x); ffma2(accA[r][1], d, wA[2].y);
                d = dup2(a4.w); ffma2(accA[r][0], d, wA[3].x); ffma2(accA[r][1], d, wA[3].y);
                d = dup2(b4.x); ffma2(accB[r][0], d, wB[0].x); ffma2(accB[r][1], d, wB[0].y);
                d = dup2(b4.y); ffma2(accB[r][0], d, wB[1].x); ffma2(accB[r][1], d, wB[1].y);
                d = dup2(b4.z); ffma2(accB[r][0], d, wB[2].x); ffma2(accB[r][1], d, wB[2].y);
                d = dup2(b4.w); ffma2(accB[r][0], d, wB[3].x); ffma2(accB[r][1], d, wB[3].y);
            }
        }
#pragma unroll
        for (int r = 0; r < 4; r++) {
            int row = rbase + r0 + r;
            if (row < NN) {
                *reinterpret_cast<ulonglong2*>(&out[(size_t)row * D + c0]) =
                    make_ulonglong2(accA[r][0], accA[r][1]);
                *reinterpret_cast<ulonglong2*>(&out[(size_t)(NN + row) * D + c0]) =
                    make_ulonglong2(accB[r][0], accB[r][1]);
            }
        }
    }
}

// ---------------- launch ----------------
extern "C" void kernel_launch(void* const* d_in, const int* in_sizes, int n_in,
                              void* d_out, int out_size) {
    const int*   q_rel     = (const int*)  d_in[1];
    const int*   q_tau     = (const int*)  d_in[2];
    const float* hidden    = (const float*)d_in[3];
    const int*   edges     = (const int*)  d_in[4];
    const float* rela      = (const float*)d_in[7];
    const float* Ws_w      = (const float*)d_in[8];
    const float* Wr_w      = (const float*)d_in[9];
    const float* Wqr_w     = (const float*)d_in[10];
    const float* Wqr_b     = (const float*)d_in[11];
    const float* Wtau_w    = (const float*)d_in[12];
    const float* w_alpha_w = (const float*)d_in[13];
    const float* w_alpha_b = (const float*)d_in[14];
    const float* W_h_w     = (const float*)d_in[15];
    const float* W_h_s_w   = (const float*)d_in[16];
    const float* wt1       = (const float*)d_in[17];
    const float* bt1       = (const float*)d_in[18];
    const float* wt2       = (const float*)d_in[19];
    const float* bt2       = (const float*)d_in[20];
    float* out = (float*)d_out;

    int prep_smem = (128 * A + 64 * 132) * (int)sizeof(float);            // 66560
    int epi_smem  = (2 * 16384 + 2 * 8448) * (int)sizeof(float);          // 198656
    cudaFuncSetAttribute(prep_kernel, cudaFuncAttributeMaxDynamicSharedMemorySize, prep_smem);
    cudaFuncSetAttribute(epi_kernel,  cudaFuncAttributeMaxDynamicSharedMemorySize, epi_smem);

    prep_kernel<<<PREP_GRID, 256, prep_smem>>>(hidden, Ws_w, rela, q_rel,
                                               Wr_w, Wtau_w, Wqr_w, Wqr_b,
                                               wt1, bt1, wt2, bt2, q_tau);
    edge_kernel<<<NE / 8, 256>>>(hidden, edges, rela, w_alpha_w, w_alpha_b, q_tau);
    epi_kernel<<<148, 512, epi_smem>>>(W_h_w, W_h_s_w, out);
}

// round 7
// speedup vs baseline: 1.9408x; 1.0320x over previous
#include <cuda_runtime.h>
#include <math.h>

#define NN 100000   // nodes
#define NE 500000   // edges
#define D  128      // in/out dim
#define A  64       // attn dim
#define NR 401      // rela vocab
#define NQ 64       // queries
#define NT 366      // tau table

#define STAB_B 782          // ceil(NN/128)
#define TAB_B  105
#define ZERO_B 256
#define PREP_GRID (STAB_B + TAB_B + ZERO_B)
#define NTILE 782           // ceil(NN/128) output tiles

typedef unsigned long long ull;

// ---------------- device scratch ----------------
__device__ float g_agg [NN * D];
__device__ float g_aggs[NN * D];
__device__ float g_stab[NN * A];
__device__ float g_rattn[NR * A];
__device__ float g_qrattn[NQ * A];
__device__ float g_tattn[NT * A];
__device__ float g_htau [NT * D];

// ---------------- f32x2 helpers (B300 FFMA2) ----------------
__device__ __forceinline__ ull dup2(float a) {
    ull r; asm("mov.b64 %0, {%1,%1};" : "=l"(r) : "f"(a)); return r;
}
__device__ __forceinline__ void ffma2(ull& acc, ull a, ull b) {
    asm("fma.rn.f32x2 %0, %1, %2, %0;" : "+l"(acc) : "l"(a), "l"(b));
}

// ---------------- h_tau table (launch #1) ----------------
__global__ void htau_kernel(const float* __restrict__ w1, const float* __restrict__ b1,
                            const float* __restrict__ w2, const float* __restrict__ b2,
                            const int*   __restrict__ q_tau_p) {
    int t = blockIdx.x;
    int d = threadIdx.x;
    float qt = (float)q_tau_p[0];
    float delta = (float)t - qt;
    g_htau[t * D + d] = fmaf(w1[d], delta, b1[d]) + sinf(fmaf(w2[d], delta, b2[d]));
}

// ============ fused prep: stab GEMM (8x4 tiles) | small tables | zero ============
__global__ void __launch_bounds__(256) prep_kernel(
    const float* __restrict__ hidden, const float* __restrict__ Ws,
    const float* __restrict__ rela,   const int*   __restrict__ q_rel,
    const float* __restrict__ Wr,     const float* __restrict__ Wtau,
    const float* __restrict__ Wqr,    const float* __restrict__ Wqr_b,
    const float* __restrict__ w1, const float* __restrict__ b1,
    const float* __restrict__ w2, const float* __restrict__ b2,
    const int* __restrict__ q_tau_p)
{
    extern __shared__ float sm[];
    int b = blockIdx.x;
    int tid = threadIdx.x;

    if (b < STAB_B) {
        // g_stab = hidden @ Ws : 128-row tile, thread = 8r x 4c, f32x2
        float* Wsm = sm;               // 128*64 floats
        float* As  = sm + 128 * A;     // 128*132 floats
        for (int i = tid; i < 128 * A / 4; i += 256)
            reinterpret_cast<float4*>(Wsm)[i] = reinterpret_cast<const float4*>(Ws)[i];
        int rbase = b * 128;
#pragma unroll
        for (int i = 0; i < 16; i++) {
            int fid = tid + i * 256;
            int r = fid >> 5, c4 = fid & 31;
            float4 v = make_float4(0.f, 0.f, 0.f, 0.f);
            if (rbase + r < NN)
                v = __ldg(reinterpret_cast<const float4*>(hidden + (size_t)(rbase + r) * D) + c4);
            *reinterpret_cast<float4*>(&As[r * 132 + c4 * 4]) = v;
        }
        __syncthreads();
        int tx = tid & 15, ty = tid >> 4;
        int c0 = tx * 4, r0 = ty * 8;
        ull acc[8][2];
#pragma unroll
        for (int r = 0; r < 8; r++) { acc[r][0] = 0ull; acc[r][1] = 0ull; }
#pragma unroll 4
        for (int kk = 0; kk < 32; kk++) {
            int k0 = kk * 4;
            ulonglong2 w[4];
#pragma unroll
            for (int j = 0; j < 4; j++)
                w[j] = *reinterpret_cast<const ulonglong2*>(&Wsm[(k0 + j) * A + c0]);
            float4 a[8];
#pragma unroll
            for (int r = 0; r < 8; r++)
                a[r] = *reinterpret_cast<const float4*>(&As[(r0 + r) * 132 + k0]);
#pragma unroll
            for (int r = 0; r < 8; r++) {
                ull d;
                d = dup2(a[r].x); ffma2(acc[r][0], d, w[0].x); ffma2(acc[r][1], d, w[0].y);
                d = dup2(a[r].y); ffma2(acc[r][0], d, w[1].x); ffma2(acc[r][1], d, w[1].y);
                d = dup2(a[r].z); ffma2(acc[r][0], d, w[2].x); ffma2(acc[r][1], d, w[2].y);
                d = dup2(a[r].w); ffma2(acc[r][0], d, w[3].x); ffma2(acc[r][1], d, w[3].y);
            }
        }
#pragma unroll
        for (int r = 0; r < 8; r++) {
            int row = rbase + r0 + r;
            if (row < NN)
                *reinterpret_cast<ulonglong2*>(&g_stab[(size_t)row * A + c0]) =
                    make_ulonglong2(acc[r][0], acc[r][1]);
        }
        return;
    }
    b -= STAB_B;

    if (b < TAB_B) {
        // small attention tables: rattn / tattn (inline h_tau) / qrattn
        float* Wsm = sm;
        float* rowbuf = sm + D * A;
        const float* src = nullptr; const float* W; const float* bias = nullptr;
        const int* gather = nullptr;
        float* out; int rows; int base; int nblk; bool comp_tau = false;
        if (b < 51)      { src = rela; W = Wr;   out = g_rattn;  rows = NR; base = 0;  nblk = 51; }
        else if (b < 97) { comp_tau = true; W = Wtau; out = g_tattn; rows = NT; base = 51; nblk = 46; }
        else             { src = rela; W = Wqr; bias = Wqr_b; gather = q_rel;
                           out = g_qrattn; rows = NQ; base = 97; nblk = 8; }

        for (int i = tid; i < D * A; i += 256) Wsm[i] = W[i];
        __syncthreads();
        int warp = tid >> 5, lane = tid & 31;
        float b0 = 0.f, b1v = 0.f;
        if (bias) { b0 = bias[2 * lane]; b1v = bias[2 * lane + 1]; }
        float qt = (float)__ldg(q_tau_p);
        int gwarp = (b - base) * 8 + warp;
        int nwarps = nblk * 8;
        for (int r = gwarp; r < rows; r += nwarps) {
            if (comp_tau) {
                float delta = (float)r - qt;
                float4 a1 = __ldg(reinterpret_cast<const float4*>(w1) + lane);
                float4 c1 = __ldg(reinterpret_cast<const float4*>(b1) + lane);
                float4 a2 = __ldg(reinterpret_cast<const float4*>(w2) + lane);
                float4 c2 = __ldg(reinterpret_cast<const float4*>(b2) + lane);
                float4 v;
                v.x = fmaf(a1.x, delta, c1.x) + sinf(fmaf(a2.x, delta, c2.x));
                v.y = fmaf(a1.y, delta, c1.y) + sinf(fmaf(a2.y, delta, c2.y));
                v.z = fmaf(a1.z, delta, c1.z) + sinf(fmaf(a2.z, delta, c2.z));
                v.w = fmaf(a1.w, delta, c1.w) + sinf(fmaf(a2.w, delta, c2.w));
                reinterpret_cast<float4*>(&rowbuf[warp * D])[lane] = v;
            } else {
                int srow = gather ? gather[r] : r;
                reinterpret_cast<float4*>(&rowbuf[warp * D])[lane] =
                    reinterpret_cast<const float4*>(src + (size_t)srow * D)[lane];
            }
            __syncwarp();
            float a0 = b0, a1s = b1v;
#pragma unroll 4
            for (int k = 0; k < D; k++) {
                float h = rowbuf[warp * D + k];
                float2 w = *reinterpret_cast<const float2*>(&Wsm[k * A + 2 * lane]);
                a0  = fmaf(h, w.x, a0);
                a1s = fmaf(h, w.y, a1s);
            }
            *reinterpret_cast<float2*>(&out[(size_t)r * A + 2 * lane]) = make_float2(a0, a1s);
            __syncwarp();
        }
        return;
    }
    b -= TAB_B;

    // zero accumulators
    size_t i = (size_t)b * 256 + tid;
    size_t n4 = (size_t)NN * D / 4;
    size_t stride = (size_t)ZERO_B * 256;
    float4 z = make_float4(0.f, 0.f, 0.f, 0.f);
    for (size_t j = i; j < n4; j += stride) {
        reinterpret_cast<float4*>(g_agg)[j]  = z;
        reinterpret_cast<float4*>(g_aggs)[j] = z;
    }
}

// ---------------- edge scatter (unchanged) ----------------
__device__ __forceinline__ void red4(float* p, float4 v) {
    asm volatile("red.global.add.v4.f32 [%0], {%1,%2,%3,%4};"
                 :: "l"(p), "f"(v.x), "f"(v.y), "f"(v.z), "f"(v.w) : "memory");
}

__global__ void edge_kernel(const float* __restrict__ hidden, const int* __restrict__ edges,
                            const float* __restrict__ rela,
                            const float* __restrict__ w_alpha, const float* __restrict__ w_alpha_b,
                            const int* __restrict__ q_tau_p) {
    int gw = (blockIdx.x * blockDim.x + threadIdx.x) >> 5;
    int lane = threadIdx.x & 31;
    if (gw >= NE) return;
    const int* e = edges + (size_t)gw * 7;
    int ridx = __ldg(e + 0);
    int rel  = __ldg(e + 2);
    int tau  = __ldg(e + 4);
    int sub  = __ldg(e + 5);
    int obj  = __ldg(e + 6);
    int qt = __ldg(q_tau_p);
    int t = (tau >= 0) ? tau : qt;

    float a0 = g_stab[(size_t)sub * A + lane]      + g_rattn[rel * A + lane]
             + g_qrattn[ridx * A + lane]           + g_tattn[t * A + lane];
    float a1 = g_stab[(size_t)sub * A + 32 + lane] + g_rattn[rel * A + 32 + lane]
             + g_qrattn[ridx * A + 32 + lane]      + g_tattn[t * A + 32 + lane];
    a0 = fmaxf(a0, 0.f);
    a1 = fmaxf(a1, 0.f);
    float p = fmaf(a0, __ldg(w_alpha + lane), a1 * __ldg(w_alpha + 32 + lane));
#pragma unroll
    for (int o = 16; o; o >>= 1) p += __shfl_xor_sync(0xffffffffu, p, o);
    float alpha = 1.f / (1.f + expf(-(p + __ldg(w_alpha_b))));
    float oma = 1.f - alpha;

    float4 hs = __ldg(reinterpret_cast<const float4*>(hidden + (size_t)sub * D) + lane);
    float4 hr = __ldg(reinterpret_cast<const float4*>(rela + (size_t)rel * D) + lane);
    float4 ht = *(reinterpret_cast<const float4*>(g_htau + (size_t)t * D) + lane);
    float4 m = make_float4(hs.x + hr.x + ht.x, hs.y + hr.y + ht.y,
                           hs.z + hr.z + ht.z, hs.w + hr.w + ht.w);
    float4 mm = make_float4(alpha * m.x, alpha * m.y, alpha * m.z, alpha * m.w);
    float4 ms = make_float4(oma * m.x, oma * m.y, oma * m.z, oma * m.w);

    red4(g_agg  + (size_t)obj * D + lane * 4, mm);
    red4(g_aggs + (size_t)obj * D + lane * 4, ms);
}

// ---------------- epilogue GEMM: one weight matrix per block ----------------
// grid 296: mat = bx&1 (0: agg@Wh -> out[0:NN], 1: aggs@Whs -> out[NN:2NN])
// 128x128 A tile, 256 threads, thread = 8r x 8c, f32x2 accumulators.
__global__ void __launch_bounds__(256) epi_kernel(const float* __restrict__ Wh,
                                                  const float* __restrict__ Whs,
                                                  float* __restrict__ out) {
    extern __shared__ float sm[];
    float* Wsm = sm;                // 128*128 = 16384 floats
    float* As  = sm + 16384;        // 128*132 = 16896 floats
    int tid = threadIdx.x;
    int mat = blockIdx.x & 1;
    const float* W    = mat ? Whs : Wh;
    const float* Asrc = mat ? g_aggs : g_agg;
    size_t obase0 = mat ? (size_t)NN * D : 0;

    for (int i = tid; i < 16384 / 4; i += 256)
        reinterpret_cast<float4*>(Wsm)[i] = reinterpret_cast<const float4*>(W)[i];

    int tx = tid & 15, ty = tid >> 4;
    int c0 = tx * 8, r0 = ty * 8;

    for (int tile = blockIdx.x >> 1; tile < NTILE; tile += 148) {
        int rbase = tile * 128;
        __syncthreads();   // covers W load on first iter; As reuse after
#pragma unroll
        for (int i = 0; i < 16; i++) {
            int fid = tid + i * 256;
            int r = fid >> 5, c4 = fid & 31;
            float4 v = make_float4(0.f, 0.f, 0.f, 0.f);
            if (rbase + r < NN)
                v = reinterpret_cast<const float4*>(Asrc + (size_t)(rbase + r) * D)[c4];
            *reinterpret_cast<float4*>(&As[r * 132 + c4 * 4]) = v;
        }
        __syncthreads();

        ull acc[8][4];
#pragma unroll
        for (int r = 0; r < 8; r++) {
            acc[r][0] = 0ull; acc[r][1] = 0ull; acc[r][2] = 0ull; acc[r][3] = 0ull;
        }
#pragma unroll 2
        for (int kk = 0; kk < 32; kk++) {
            int k0 = kk * 4;
            float4 a[8];
#pragma unroll
            for (int r = 0; r < 8; r++)
                a[r] = *reinterpret_cast<const float4*>(&As[(r0 + r) * 132 + k0]);
#pragma unroll
            for (int j = 0; j < 4; j++) {
                ulonglong2 w0 = *reinterpret_cast<const ulonglong2*>(&Wsm[(k0 + j) * 128 + c0]);
                ulonglong2 w1 = *reinterpret_cast<const ulonglong2*>(&Wsm[(k0 + j) * 128 + c0 + 4]);
#pragma unroll
                for (int r = 0; r < 8; r++) {
                    float av = (j == 0) ? a[r].x : (j == 1) ? a[r].y : (j == 2) ? a[r].z : a[r].w;
                    ull d = dup2(av);
                    ffma2(acc[r][0], d, w0.x); ffma2(acc[r][1], d, w0.y);
                    ffma2(acc[r][2], d, w1.x); ffma2(acc[r][3], d, w1.y);
                }
            }
        }
#pragma unroll
        for (int r = 0; r < 8; r++) {
            int row = rbase + r0 + r;
            if (row < NN) {
                float* op = out + obase0 + (size_t)row * D + c0;
                *reinterpret_cast<ulonglong2*>(op)     = make_ulonglong2(acc[r][0], acc[r][1]);
                *reinterpret_cast<ulonglong2*>(op + 4) = make_ulonglong2(acc[r][2], acc[r][3]);
            }
        }
    }
}

// ---------------- launch ----------------
extern "C" void kernel_launch(void* const* d_in, const int* in_sizes, int n_in,
                              void* d_out, int out_size) {
    const int*   q_rel     = (const int*)  d_in[1];
    const int*   q_tau     = (const int*)  d_in[2];
    const float* hidden    = (const float*)d_in[3];
    const int*   edges     = (const int*)  d_in[4];
    const float* rela      = (const float*)d_in[7];
    const float* Ws_w      = (const float*)d_in[8];
    const float* Wr_w      = (const float*)d_in[9];
    const float* Wqr_w     = (const float*)d_in[10];
    const float* Wqr_b     = (const float*)d_in[11];
    const float* Wtau_w    = (const float*)d_in[12];
    const float* w_alpha_w = (const float*)d_in[13];
    const float* w_alpha_b = (const float*)d_in[14];
    const float* W_h_w     = (const float*)d_in[15];
    const float* W_h_s_w   = (const float*)d_in[16];
    const float* wt1       = (const float*)d_in[17];
    const float* bt1       = (const float*)d_in[18];
    const float* wt2       = (const float*)d_in[19];
    const float* bt2       = (const float*)d_in[20];
    float* out = (float*)d_out;

    int prep_smem = (128 * A + 128 * 132) * (int)sizeof(float);       // 100352 B
    int epi_smem  = (16384 + 128 * 132) * (int)sizeof(float);         // 133120 B
    cudaFuncSetAttribute(prep_kernel, cudaFuncAttributeMaxDynamicSharedMemorySize, prep_smem);
    cudaFuncSetAttribute(epi_kernel,  cudaFuncAttributeMaxDynamicSharedMemorySize, epi_smem);

    htau_kernel<<<NT, D>>>(wt1, bt1, wt2, bt2, q_tau);                       // launch 1
    prep_kernel<<<PREP_GRID, 256, prep_smem>>>(hidden, Ws_w, rela, q_rel,    // launch 2
                                               Wr_w, Wtau_w, Wqr_w, Wqr_b,
                                               wt1, bt1, wt2, bt2, q_tau);
    edge_kernel<<<NE / 8, 256>>>(hidden, edges, rela, w_alpha_w, w_alpha_b, q_tau); // launch 3
    epi_kernel<<<296, 256, epi_smem>>>(W_h_w, W_h_s_w, out);                 // launch 4 (profiled)
}